// round 7
// baseline (speedup 1.0000x reference)
#include <cuda_runtime.h>
#include <cuda_fp16.h>
#include <math.h>

#define NN      50000
#define EE      1600000
#define FIN     256
#define H       4
#define D       32
#define HD      128
#define C       16
#define NBLK    196     // ceil(NN/256)

// ---------------- scratch ------------------------------------------------
__device__ __align__(16) __half g_feat1h[NN * HD];
__device__ __align__(16) float g_el1[NN * H];
__device__ __align__(16) float g_er1[NN * H];
__device__ __align__(16) float g_h[NN * HD];
__device__ __align__(16) __half g_feat2h[NN * C];
__device__ __align__(16) float g_el2[NN];
__device__ __align__(16) float g_er2[NN];
// CSR build
__device__ int g_cnt[NN];
__device__ int g_off[NN + 1];
__device__ int g_cur[NN];
__device__ int g_ebuf[EE];
__device__ int g_bsum[NBLK];
__device__ int g_bpre[NBLK + 1];

__device__ __forceinline__ float lrelu(float v) { return v > 0.f ? v : 0.2f * v; }
__device__ __forceinline__ float elu1(float v)  { return v > 0.f ? v : (__expf(v) - 1.f); }

__device__ __forceinline__ unsigned f2tf32(float f) {
    unsigned r;
    asm("cvt.rna.tf32.f32 %0, %1;" : "=r"(r) : "f"(f));
    return r;
}

__device__ __forceinline__ void mma_tf32(float c[4],
                                         unsigned a0, unsigned a1, unsigned a2, unsigned a3,
                                         unsigned b0, unsigned b1) {
    asm volatile("mma.sync.aligned.m16n8k8.row.col.f32.tf32.tf32.f32 "
                 "{%0,%1,%2,%3}, {%4,%5,%6,%7}, {%8,%9}, {%0,%1,%2,%3};"
                 : "+f"(c[0]), "+f"(c[1]), "+f"(c[2]), "+f"(c[3])
                 : "r"(a0), "r"(a1), "r"(a2), "r"(a3), "r"(b0), "r"(b1));
}

// ---------------- CSR build ---------------------------------------------
__global__ void k_zero_cnt() {
    int i = blockIdx.x * blockDim.x + threadIdx.x;
    if (i < NN) g_cnt[i] = 0;
}

__global__ void k_hist(const int* __restrict__ dst, int e_cnt) {
    int e = blockIdx.x * blockDim.x + threadIdx.x;
    if (e < e_cnt) atomicAdd(&g_cnt[dst[e]], 1);
}

__global__ void k_scan1() {
    __shared__ int sh[256];
    int t = threadIdx.x;
    int i = blockIdx.x * 256 + t;
    int v = (i < NN) ? g_cnt[i] : 0;
    sh[t] = v;
    __syncthreads();
#pragma unroll
    for (int ofs = 1; ofs < 256; ofs <<= 1) {
        int x = (t >= ofs) ? sh[t - ofs] : 0;
        __syncthreads();
        sh[t] += x;
        __syncthreads();
    }
    if (i < NN) g_off[i] = sh[t] - v;
    if (t == 255) g_bsum[blockIdx.x] = sh[255];
}

__global__ void k_scan2() {
    __shared__ int sh[256];
    int t = threadIdx.x;
    int v = (t < NBLK) ? g_bsum[t] : 0;
    sh[t] = v;
    __syncthreads();
#pragma unroll
    for (int ofs = 1; ofs < 256; ofs <<= 1) {
        int x = (t >= ofs) ? sh[t - ofs] : 0;
        __syncthreads();
        sh[t] += x;
        __syncthreads();
    }
    if (t < NBLK) g_bpre[t] = sh[t] - v;
}

__global__ void k_scan3(int e_cnt) {
    int i = blockIdx.x * blockDim.x + threadIdx.x;
    if (i < NN) {
        int o = g_off[i] + g_bpre[i >> 8];
        g_off[i] = o;
        g_cur[i] = o;
    }
    if (i == 0) g_off[NN] = e_cnt;
}

__global__ void k_scatter(const int* __restrict__ src, const int* __restrict__ dst, int e_cnt) {
    int e = blockIdx.x * blockDim.x + threadIdx.x;
    if (e >= e_cnt) return;
    int pos = atomicAdd(&g_cur[dst[e]], 1);
    g_ebuf[pos] = src[e];
}

// ---------------- K1: feat1 = x @ W1 via TF32 tensor cores --------------
// 128x128 tile per block, 8 warps, each warp 16 rows x 128 cols.
// 3-mma split (x_hi*w_hi + x_hi*w_lo + x_lo*w_hi) for ~fp32 accuracy.
__global__ __launch_bounds__(256) void k_gemm1_tc(const float* __restrict__ x,
                                                  const float* __restrict__ W1,
                                                  const float* __restrict__ al1,
                                                  const float* __restrict__ ar1,
                                                  int n) {
    __shared__ unsigned xs_hi[128][20], xs_lo[128][20];
    __shared__ unsigned ws_hi[16][132], ws_lo[16][132];
    __shared__ float al_s[128], ar_s[128];
    int t = threadIdx.x;
    int lane = t & 31;
    int wid = t >> 5;
    int row0 = blockIdx.x * 128;
    if (t < 128) al_s[t] = al1[t];
    else         ar_s[t - 128] = ar1[t - 128];

    float acc[16][4];
#pragma unroll
    for (int nt = 0; nt < 16; nt++) { acc[nt][0]=0.f; acc[nt][1]=0.f; acc[nt][2]=0.f; acc[nt][3]=0.f; }

    for (int kb = 0; kb < 16; kb++) {
        __syncthreads();
        // x tile: 128 rows x 16 K-cols = 512 float4
#pragma unroll
        for (int i = 0; i < 2; i++) {
            int idx = t + i * 256;
            int r = idx >> 2, c4 = (idx & 3) * 4;
            int gr = row0 + r;
            float4 v = make_float4(0.f, 0.f, 0.f, 0.f);
            if (gr < n) v = *(const float4*)&x[(long)gr * FIN + kb * 16 + c4];
            float vv[4] = {v.x, v.y, v.z, v.w};
#pragma unroll
            for (int j = 0; j < 4; j++) {
                unsigned hu = f2tf32(vv[j]);
                xs_hi[r][c4 + j] = hu;
                xs_lo[r][c4 + j] = f2tf32(vv[j] - __uint_as_float(hu));
            }
        }
        // W tile: 16 rows x 128 cols = 512 float4
#pragma unroll
        for (int i = 0; i < 2; i++) {
            int idx = t + i * 256;
            int r = idx >> 5, c4 = (idx & 31) * 4;
            float4 v = *(const float4*)&W1[(kb * 16 + r) * HD + c4];
            float vv[4] = {v.x, v.y, v.z, v.w};
#pragma unroll
            for (int j = 0; j < 4; j++) {
                unsigned hu = f2tf32(vv[j]);
                ws_hi[r][c4 + j] = hu;
                ws_lo[r][c4 + j] = f2tf32(vv[j] - __uint_as_float(hu));
            }
        }
        __syncthreads();
#pragma unroll
        for (int k8 = 0; k8 < 2; k8++) {
            int arow = wid * 16 + (lane >> 2);
            int acol = k8 * 8 + (lane & 3);
            unsigned Ah0 = xs_hi[arow][acol],     Ah1 = xs_hi[arow + 8][acol];
            unsigned Ah2 = xs_hi[arow][acol + 4], Ah3 = xs_hi[arow + 8][acol + 4];
            unsigned Al0 = xs_lo[arow][acol],     Al1 = xs_lo[arow + 8][acol];
            unsigned Al2 = xs_lo[arow][acol + 4], Al3 = xs_lo[arow + 8][acol + 4];
            int brow = k8 * 8 + (lane & 3);
            int bc0 = lane >> 2;
#pragma unroll
            for (int nt = 0; nt < 16; nt++) {
                int bcol = nt * 8 + bc0;
                unsigned Bh0 = ws_hi[brow][bcol], Bh1 = ws_hi[brow + 4][bcol];
                unsigned Bl0 = ws_lo[brow][bcol], Bl1 = ws_lo[brow + 4][bcol];
                mma_tf32(acc[nt], Ah0, Ah1, Ah2, Ah3, Bh0, Bh1);
                mma_tf32(acc[nt], Ah0, Ah1, Ah2, Ah3, Bl0, Bl1);
                mma_tf32(acc[nt], Al0, Al1, Al2, Al3, Bh0, Bh1);
            }
        }
    }

    // epilogue: fp16 feat store + per-head el/er (reduce over lane%4 group)
#pragma unroll
    for (int rh = 0; rh < 2; rh++) {
        int gr = row0 + wid * 16 + (lane >> 2) + rh * 8;
        int ci = rh * 2;
        float el[4], er[4];
#pragma unroll
        for (int h = 0; h < 4; h++) {
            float ep = 0.f, rp = 0.f;
#pragma unroll
            for (int j = 0; j < 4; j++) {
                int nt = h * 4 + j;
                int col0 = nt * 8 + 2 * (lane & 3);
                ep += acc[nt][ci] * al_s[col0] + acc[nt][ci + 1] * al_s[col0 + 1];
                rp += acc[nt][ci] * ar_s[col0] + acc[nt][ci + 1] * ar_s[col0 + 1];
            }
            ep += __shfl_xor_sync(0xffffffffu, ep, 1);
            ep += __shfl_xor_sync(0xffffffffu, ep, 2);
            rp += __shfl_xor_sync(0xffffffffu, rp, 1);
            rp += __shfl_xor_sync(0xffffffffu, rp, 2);
            el[h] = ep; er[h] = rp;
        }
        if (gr < n) {
#pragma unroll
            for (int nt = 0; nt < 16; nt++) {
                __half2 hv = __floats2half2_rn(acc[nt][ci], acc[nt][ci + 1]);
                *(__half2*)&g_feat1h[(long)gr * HD + nt * 8 + 2 * (lane & 3)] = hv;
            }
            if ((lane & 3) == 0) {
                *(float4*)&g_el1[gr * 4] = make_float4(el[0], el[1], el[2], el[3]);
                *(float4*)&g_er1[gr * 4] = make_float4(er[0], er[1], er[2], er[3]);
            }
        }
    }
}

// ---------------- K2: fused layer-1, edge loop unrolled x4 --------------
__global__ __launch_bounds__(256) void k_layer1(const float* __restrict__ b1, int n) {
    int wid = (blockIdx.x * blockDim.x + threadIdx.x) >> 5;
    if (wid >= n) return;
    int lane = threadIdx.x & 31;
    int head = lane >> 3;
    long fofs = lane * 4;
    int off0 = g_off[wid], off1 = g_off[wid + 1];
    float er = g_er1[wid * 4 + head];
    float ax = 0.f, ay = 0.f, az = 0.f, aw = 0.f, wsum = 0.f;

    int j = off0;
    for (; j + 4 <= off1; j += 4) {
        int s0 = __ldg(&g_ebuf[j]);
        int s1 = __ldg(&g_ebuf[j + 1]);
        int s2 = __ldg(&g_ebuf[j + 2]);
        int s3 = __ldg(&g_ebuf[j + 3]);
        float e0 = __ldg(&g_el1[s0 * 4 + head]);
        float e1 = __ldg(&g_el1[s1 * 4 + head]);
        float e2 = __ldg(&g_el1[s2 * 4 + head]);
        float e3 = __ldg(&g_el1[s3 * 4 + head]);
        uint2 p0 = *(const uint2*)&g_feat1h[(long)s0 * HD + fofs];
        uint2 p1 = *(const uint2*)&g_feat1h[(long)s1 * HD + fofs];
        uint2 p2 = *(const uint2*)&g_feat1h[(long)s2 * HD + fofs];
        uint2 p3 = *(const uint2*)&g_feat1h[(long)s3 * HD + fofs];
        float w0 = __expf(lrelu(e0 + er));
        float w1 = __expf(lrelu(e1 + er));
        float w2 = __expf(lrelu(e2 + er));
        float w3 = __expf(lrelu(e3 + er));
        wsum += (w0 + w1) + (w2 + w3);
        float2 a0 = __half22float2(*(__half2*)&p0.x), b0 = __half22float2(*(__half2*)&p0.y);
        float2 a1 = __half22float2(*(__half2*)&p1.x), b1v = __half22float2(*(__half2*)&p1.y);
        float2 a2 = __half22float2(*(__half2*)&p2.x), b2v = __half22float2(*(__half2*)&p2.y);
        float2 a3 = __half22float2(*(__half2*)&p3.x), b3v = __half22float2(*(__half2*)&p3.y);
        ax += a0.x * w0 + a1.x * w1 + a2.x * w2 + a3.x * w3;
        ay += a0.y * w0 + a1.y * w1 + a2.y * w2 + a3.y * w3;
        az += b0.x * w0 + b1v.x * w1 + b2v.x * w2 + b3v.x * w3;
        aw += b0.y * w0 + b1v.y * w1 + b2v.y * w2 + b3v.y * w3;
    }
    for (; j < off1; j++) {
        int s = __ldg(&g_ebuf[j]);
        float el = __ldg(&g_el1[s * 4 + head]);
        uint2 p = *(const uint2*)&g_feat1h[(long)s * HD + fofs];
        float w = __expf(lrelu(el + er));
        float2 f01 = __half22float2(*(__half2*)&p.x);
        float2 f23 = __half22float2(*(__half2*)&p.y);
        ax += f01.x * w; ay += f01.y * w; az += f23.x * w; aw += f23.y * w;
        wsum += w;
    }
    float inv = 1.f / fmaxf(wsum, 1e-9f);
    float4 b = *(const float4*)&b1[lane * 4];
    float4 o;
    o.x = elu1(ax * inv + b.x);
    o.y = elu1(ay * inv + b.y);
    o.z = elu1(az * inv + b.z);
    o.w = elu1(aw * inv + b.w);
    *(float4*)&g_h[(long)wid * HD + lane * 4] = o;
}

// ---------------- K3: feat2 = h @ W2 + el2/er2 --------------------------
__global__ __launch_bounds__(256) void k_gemm2(const float* __restrict__ W2,
                                               const float* __restrict__ al2,
                                               const float* __restrict__ ar2, int n) {
    __shared__ float w2s[HD * C];
    __shared__ float al2s[C], ar2s[C];
    int t = threadIdx.x;
    for (int j = t; j < HD * C; j += 256) w2s[j] = W2[j];
    if (t < C) { al2s[t] = al2[t]; ar2s[t] = ar2[t]; }
    __syncthreads();
    int node = blockIdx.x * 256 + t;
    if (node >= n) return;
    float acc[C];
#pragma unroll
    for (int c = 0; c < C; c++) acc[c] = 0.f;
    const float* hr = &g_h[(long)node * HD];
#pragma unroll 4
    for (int kk = 0; kk < 32; kk++) {
        float4 f = *(const float4*)&hr[kk * 4];
        const float* wrow = &w2s[(kk * 4) * C];
#pragma unroll
        for (int c = 0; c < C; c++) {
            acc[c] += f.x * wrow[c] + f.y * wrow[C + c] + f.z * wrow[2 * C + c] + f.w * wrow[3 * C + c];
        }
    }
    float el = 0.f, er = 0.f;
#pragma unroll
    for (int c = 0; c < C; c++) { el += acc[c] * al2s[c]; er += acc[c] * ar2s[c]; }
    __half* outp = &g_feat2h[(long)node * C];
#pragma unroll
    for (int c2 = 0; c2 < 8; c2++) {
        __half2 hv = __floats2half2_rn(acc[c2 * 2], acc[c2 * 2 + 1]);
        *(__half2*)&outp[c2 * 2] = hv;
    }
    g_el2[node] = el;
    g_er2[node] = er;
}

// ---------------- K4: fused layer-2, edge loop unrolled x4 --------------
__global__ __launch_bounds__(256) void k_layer2(const float* __restrict__ b2,
                                                float* __restrict__ out, int n) {
    int t = threadIdx.x;
    int d = blockIdx.x * 16 + (t >> 4);
    if (d >= n) return;
    int c = t & 15;
    int off0 = g_off[d], off1 = g_off[d + 1];
    float er = g_er2[d];
    float acc = 0.f, wsum = 0.f;

    int j = off0;
    for (; j + 4 <= off1; j += 4) {
        int s0 = __ldg(&g_ebuf[j]);
        int s1 = __ldg(&g_ebuf[j + 1]);
        int s2 = __ldg(&g_ebuf[j + 2]);
        int s3 = __ldg(&g_ebuf[j + 3]);
        float e0 = __ldg(&g_el2[s0]);
        float e1 = __ldg(&g_el2[s1]);
        float e2 = __ldg(&g_el2[s2]);
        float e3 = __ldg(&g_el2[s3]);
        float f0 = __half2float(g_feat2h[(long)s0 * C + c]);
        float f1 = __half2float(g_feat2h[(long)s1 * C + c]);
        float f2 = __half2float(g_feat2h[(long)s2 * C + c]);
        float f3 = __half2float(g_feat2h[(long)s3 * C + c]);
        float w0 = __expf(lrelu(e0 + er));
        float w1 = __expf(lrelu(e1 + er));
        float w2 = __expf(lrelu(e2 + er));
        float w3 = __expf(lrelu(e3 + er));
        acc += f0 * w0 + f1 * w1 + f2 * w2 + f3 * w3;
        wsum += (w0 + w1) + (w2 + w3);
    }
    for (; j < off1; j++) {
        int s = __ldg(&g_ebuf[j]);
        float el = __ldg(&g_el2[s]);
        float f = __half2float(g_feat2h[(long)s * C + c]);
        float w = __expf(lrelu(el + er));
        acc += f * w;
        wsum += w;
    }
    out[(long)d * C + c] = acc / fmaxf(wsum, 1e-9f) + __ldg(&b2[c]);
}

extern "C" void kernel_launch(void* const* d_in, const int* in_sizes, int n_in,
                              void* d_out, int out_size) {
    const float* x   = (const float*)d_in[0];
    const int*   src = (const int*)d_in[1];
    const int*   dst = (const int*)d_in[2];
    const float* W1  = (const float*)d_in[3];
    const float* b1  = (const float*)d_in[4];
    const float* al1 = (const float*)d_in[5];
    const float* ar1 = (const float*)d_in[6];
    const float* W2  = (const float*)d_in[7];
    const float* b2  = (const float*)d_in[8];
    const float* al2 = (const float*)d_in[9];
    const float* ar2 = (const float*)d_in[10];
    float* out = (float*)d_out;

    int n = in_sizes[0] / FIN;   // 50000
    int e = in_sizes[1];         // 1600000
    int eb = (e + 255) / 256;

    k_zero_cnt<<<NBLK, 256>>>();
    k_gemm1_tc<<<(n + 127) / 128, 256>>>(x, W1, al1, ar1, n);
    k_hist<<<eb, 256>>>(dst, e);
    k_scan1<<<NBLK, 256>>>();
    k_scan2<<<1, 256>>>();
    k_scan3<<<NBLK, 256>>>(e);
    k_scatter<<<eb, 256>>>(src, dst, e);

    k_layer1<<<(n * 32 + 255) / 256, 256>>>(b1, n);
    k_gemm2<<<(n + 255) / 256, 256>>>(W2, al2, ar2, n);
    k_layer2<<<(n * 16 + 255) / 256, 256>>>(b2, out, n);
}

// round 8
// speedup vs baseline: 1.3063x; 1.3063x over previous
#include <cuda_runtime.h>
#include <cuda_fp16.h>
#include <math.h>

#define NN      50000
#define EE      1600000
#define FIN     256
#define H       4
#define D       32
#define HD      128
#define C       16
#define NBLK    196     // ceil(NN/256)

// ---------------- scratch ------------------------------------------------
__device__ __align__(16) __half g_feat1h[NN * HD];
__device__ __align__(16) float g_el1[NN * H];
__device__ __align__(16) float g_er1[NN * H];
__device__ __align__(16) float g_h[NN * HD];
__device__ __align__(16) __half g_feat2h[NN * C];
__device__ __align__(16) float g_el2[NN];
__device__ __align__(16) float g_er2[NN];
// CSR build
__device__ int g_cnt[NN];
__device__ int g_off[NN + 1];
__device__ int g_cur[NN];
__device__ int g_ebuf[EE];
__device__ int g_bsum[NBLK];
__device__ int g_bpre[NBLK + 1];

__device__ __forceinline__ float lrelu(float v) { return v > 0.f ? v : 0.2f * v; }
__device__ __forceinline__ float elu1(float v)  { return v > 0.f ? v : (__expf(v) - 1.f); }

__device__ __forceinline__ void mma_f16(float c[4], unsigned a0, unsigned a1,
                                        unsigned a2, unsigned a3,
                                        unsigned b0, unsigned b1) {
    asm volatile("mma.sync.aligned.m16n8k16.row.col.f32.f16.f16.f32 "
                 "{%0,%1,%2,%3}, {%4,%5,%6,%7}, {%8,%9}, {%0,%1,%2,%3};"
                 : "+f"(c[0]), "+f"(c[1]), "+f"(c[2]), "+f"(c[3])
                 : "r"(a0), "r"(a1), "r"(a2), "r"(a3), "r"(b0), "r"(b1));
}

// split float2 -> fp16 hi + fp16 lo (packed half2 as unsigned)
__device__ __forceinline__ void split2(float2 v, unsigned& hi, unsigned& lo) {
    __half2 h = __floats2half2_rn(v.x, v.y);
    float2 hb = __half22float2(h);
    __half2 l = __floats2half2_rn(v.x - hb.x, v.y - hb.y);
    hi = *(unsigned*)&h;
    lo = *(unsigned*)&l;
}

// ---------------- CSR build ---------------------------------------------
__global__ void k_zero_cnt() {
    int i = blockIdx.x * blockDim.x + threadIdx.x;
    if (i < NN) g_cnt[i] = 0;
}

__global__ void k_hist(const int* __restrict__ dst, int e_cnt) {
    int e = blockIdx.x * blockDim.x + threadIdx.x;
    if (e < e_cnt) atomicAdd(&g_cnt[dst[e]], 1);
}

__global__ void k_scan1() {
    __shared__ int sh[256];
    int t = threadIdx.x;
    int i = blockIdx.x * 256 + t;
    int v = (i < NN) ? g_cnt[i] : 0;
    sh[t] = v;
    __syncthreads();
#pragma unroll
    for (int ofs = 1; ofs < 256; ofs <<= 1) {
        int x = (t >= ofs) ? sh[t - ofs] : 0;
        __syncthreads();
        sh[t] += x;
        __syncthreads();
    }
    if (i < NN) g_off[i] = sh[t] - v;
    if (t == 255) g_bsum[blockIdx.x] = sh[255];
}

__global__ void k_scan2() {
    __shared__ int sh[256];
    int t = threadIdx.x;
    int v = (t < NBLK) ? g_bsum[t] : 0;
    sh[t] = v;
    __syncthreads();
#pragma unroll
    for (int ofs = 1; ofs < 256; ofs <<= 1) {
        int x = (t >= ofs) ? sh[t - ofs] : 0;
        __syncthreads();
        sh[t] += x;
        __syncthreads();
    }
    if (t < NBLK) g_bpre[t] = sh[t] - v;
}

__global__ void k_scan3(int e_cnt) {
    int i = blockIdx.x * blockDim.x + threadIdx.x;
    if (i < NN) {
        int o = g_off[i] + g_bpre[i >> 8];
        g_off[i] = o;
        g_cur[i] = o;
    }
    if (i == 0) g_off[NN] = e_cnt;
}

__global__ void k_scatter(const int* __restrict__ src, const int* __restrict__ dst, int e_cnt) {
    int e = blockIdx.x * blockDim.x + threadIdx.x;
    if (e >= e_cnt) return;
    int pos = atomicAdd(&g_cur[dst[e]], 1);
    g_ebuf[pos] = src[e];
}

// ---------------- K1: feat1 = x @ W1 via fp16 hi/lo HMMA ---------------
// CTA: 128 rows x 128 cols, 8 warps as 4(m) x 2(n); warp = m32 x n64.
// K chunks of 32. A loaded global->reg (frag layout). B repacked to
// per-lane frag order in shared once per chunk (uint4 = hi0,hi1,lo0,lo1).
__global__ __launch_bounds__(256) void k_gemm1_tc(const float* __restrict__ x,
                                                  const float* __restrict__ W1,
                                                  const float* __restrict__ al1,
                                                  const float* __restrict__ ar1,
                                                  int n) {
    __shared__ float ws_raw[32][128];
    __shared__ uint4 wfrag[2][16][32];     // [k16][n8][lane]
    __shared__ float al_s[128], ar_s[128];
    int t = threadIdx.x;
    int lane = t & 31;
    int wid = t >> 5;
    int gid = lane >> 2;      // 0..7
    int tg = lane & 3;        // 0..3
    int warp_m = wid >> 1;    // 0..3
    int warp_n = wid & 1;     // 0..1
    int row0 = blockIdx.x * 128;
    if (t < 128) al_s[t] = al1[t];
    else         ar_s[t - 128] = ar1[t - 128];

    float acc[2][8][4];       // [m16 tile][n8 tile][frag]
#pragma unroll
    for (int m = 0; m < 2; m++)
#pragma unroll
        for (int j = 0; j < 8; j++) { acc[m][j][0]=0.f; acc[m][j][1]=0.f; acc[m][j][2]=0.f; acc[m][j][3]=0.f; }

    for (int kb = 0; kb < 8; kb++) {
        int K0 = kb * 32;
        // ---- A frags: global -> reg, hi/lo split ----
        unsigned Ahi[2][2][4], Alo[2][2][4];   // [m16][k16][4 regs]
#pragma unroll
        for (int m = 0; m < 2; m++) {
            int r = row0 + warp_m * 32 + m * 16 + gid;
            int rok0 = (r < n);
            int rok8 = (r + 8 < n);
            const float* xr0 = &x[(long)r * FIN + K0 + tg * 2];
            const float* xr8 = xr0 + 8L * FIN;
#pragma unroll
            for (int k16 = 0; k16 < 2; k16++) {
                float2 v0 = rok0 ? *(const float2*)&xr0[k16 * 16]     : make_float2(0.f, 0.f);
                float2 v1 = rok8 ? *(const float2*)&xr8[k16 * 16]     : make_float2(0.f, 0.f);
                float2 v2 = rok0 ? *(const float2*)&xr0[k16 * 16 + 8] : make_float2(0.f, 0.f);
                float2 v3 = rok8 ? *(const float2*)&xr8[k16 * 16 + 8] : make_float2(0.f, 0.f);
                split2(v0, Ahi[m][k16][0], Alo[m][k16][0]);
                split2(v1, Ahi[m][k16][1], Alo[m][k16][1]);
                split2(v2, Ahi[m][k16][2], Alo[m][k16][2]);
                split2(v3, Ahi[m][k16][3], Alo[m][k16][3]);
            }
        }
        // ---- B: coalesced load to shared ----
        __syncthreads();   // previous iteration's frag reads done
#pragma unroll
        for (int i = 0; i < 4; i++) {
            int idx = t * 4 + i * 1024;
            int r = idx >> 7, c4 = idx & 127;
            *(float4*)&ws_raw[r][c4] = *(const float4*)&W1[(K0 + r) * HD + c4];
        }
        __syncthreads();
        // ---- repack to frag order ----
#pragma unroll
        for (int i = 0; i < 4; i++) {
            int e = t + i * 256;
            int k16 = e >> 9;
            int n8 = (e >> 5) & 15;
            int ln = e & 31;
            int eg = ln >> 2, et = ln & 3;
            int col = n8 * 8 + eg;
            int kr = k16 * 16 + et * 2;
            unsigned hi0, lo0, hi1, lo1;
            split2(make_float2(ws_raw[kr][col],     ws_raw[kr + 1][col]), hi0, lo0);
            split2(make_float2(ws_raw[kr + 8][col], ws_raw[kr + 9][col]), hi1, lo1);
            wfrag[k16][n8][ln] = make_uint4(hi0, hi1, lo0, lo1);
        }
        __syncthreads();
        // ---- mma ----
#pragma unroll
        for (int k16 = 0; k16 < 2; k16++) {
#pragma unroll
            for (int j = 0; j < 8; j++) {
                uint4 q = wfrag[k16][warp_n * 8 + j][lane];
#pragma unroll
                for (int m = 0; m < 2; m++) {
                    mma_f16(acc[m][j], Ahi[m][k16][0], Ahi[m][k16][1],
                            Ahi[m][k16][2], Ahi[m][k16][3], q.x, q.y);
                    mma_f16(acc[m][j], Ahi[m][k16][0], Ahi[m][k16][1],
                            Ahi[m][k16][2], Ahi[m][k16][3], q.z, q.w);
                    mma_f16(acc[m][j], Alo[m][k16][0], Alo[m][k16][1],
                            Alo[m][k16][2], Alo[m][k16][3], q.x, q.y);
                }
            }
        }
    }

    // ---- epilogue: fp16 feat + el/er ----
#pragma unroll
    for (int m = 0; m < 2; m++) {
#pragma unroll
        for (int rv = 0; rv < 2; rv++) {     // c0/c1 row vs c2/c3 row
            int gr = row0 + warp_m * 32 + m * 16 + gid + rv * 8;
            int ci = rv * 2;
            float el0 = 0.f, er0 = 0.f, el1v = 0.f, er1v = 0.f;
#pragma unroll
            for (int j = 0; j < 8; j++) {
                int col = warp_n * 64 + j * 8 + tg * 2;
                float c0 = acc[m][j][ci], c1 = acc[m][j][ci + 1];
                float ep = c0 * al_s[col] + c1 * al_s[col + 1];
                float rp = c0 * ar_s[col] + c1 * ar_s[col + 1];
                if (j < 4) { el0 += ep; er0 += rp; }
                else       { el1v += ep; er1v += rp; }
            }
            el0 += __shfl_xor_sync(0xffffffffu, el0, 1);
            el0 += __shfl_xor_sync(0xffffffffu, el0, 2);
            er0 += __shfl_xor_sync(0xffffffffu, er0, 1);
            er0 += __shfl_xor_sync(0xffffffffu, er0, 2);
            el1v += __shfl_xor_sync(0xffffffffu, el1v, 1);
            el1v += __shfl_xor_sync(0xffffffffu, el1v, 2);
            er1v += __shfl_xor_sync(0xffffffffu, er1v, 1);
            er1v += __shfl_xor_sync(0xffffffffu, er1v, 2);
            if (gr < n) {
#pragma unroll
                for (int j = 0; j < 8; j++) {
                    int col = warp_n * 64 + j * 8 + tg * 2;
                    __half2 hv = __floats2half2_rn(acc[m][j][ci], acc[m][j][ci + 1]);
                    *(__half2*)&g_feat1h[(long)gr * HD + col] = hv;
                }
                if (tg == 0) {
                    int h0 = warp_n * 2;
                    g_el1[gr * 4 + h0] = el0;
                    g_el1[gr * 4 + h0 + 1] = el1v;
                    g_er1[gr * 4 + h0] = er0;
                    g_er1[gr * 4 + h0 + 1] = er1v;
                }
            }
        }
    }
}

// ---------------- K2: fused layer-1, edge loop unrolled x4 --------------
__global__ __launch_bounds__(256) void k_layer1(const float* __restrict__ b1, int n) {
    int wid = (blockIdx.x * blockDim.x + threadIdx.x) >> 5;
    if (wid >= n) return;
    int lane = threadIdx.x & 31;
    int head = lane >> 3;
    long fofs = lane * 4;
    int off0 = g_off[wid], off1 = g_off[wid + 1];
    float er = g_er1[wid * 4 + head];
    float ax = 0.f, ay = 0.f, az = 0.f, aw = 0.f, wsum = 0.f;

    int j = off0;
    for (; j + 4 <= off1; j += 4) {
        int s0 = __ldg(&g_ebuf[j]);
        int s1 = __ldg(&g_ebuf[j + 1]);
        int s2 = __ldg(&g_ebuf[j + 2]);
        int s3 = __ldg(&g_ebuf[j + 3]);
        float e0 = __ldg(&g_el1[s0 * 4 + head]);
        float e1 = __ldg(&g_el1[s1 * 4 + head]);
        float e2 = __ldg(&g_el1[s2 * 4 + head]);
        float e3 = __ldg(&g_el1[s3 * 4 + head]);
        uint2 p0 = *(const uint2*)&g_feat1h[(long)s0 * HD + fofs];
        uint2 p1 = *(const uint2*)&g_feat1h[(long)s1 * HD + fofs];
        uint2 p2 = *(const uint2*)&g_feat1h[(long)s2 * HD + fofs];
        uint2 p3 = *(const uint2*)&g_feat1h[(long)s3 * HD + fofs];
        float w0 = __expf(lrelu(e0 + er));
        float w1 = __expf(lrelu(e1 + er));
        float w2 = __expf(lrelu(e2 + er));
        float w3 = __expf(lrelu(e3 + er));
        wsum += (w0 + w1) + (w2 + w3);
        float2 a0 = __half22float2(*(__half2*)&p0.x), b0 = __half22float2(*(__half2*)&p0.y);
        float2 a1 = __half22float2(*(__half2*)&p1.x), b1v = __half22float2(*(__half2*)&p1.y);
        float2 a2 = __half22float2(*(__half2*)&p2.x), b2v = __half22float2(*(__half2*)&p2.y);
        float2 a3 = __half22float2(*(__half2*)&p3.x), b3v = __half22float2(*(__half2*)&p3.y);
        ax += a0.x * w0 + a1.x * w1 + a2.x * w2 + a3.x * w3;
        ay += a0.y * w0 + a1.y * w1 + a2.y * w2 + a3.y * w3;
        az += b0.x * w0 + b1v.x * w1 + b2v.x * w2 + b3v.x * w3;
        aw += b0.y * w0 + b1v.y * w1 + b2v.y * w2 + b3v.y * w3;
    }
    for (; j < off1; j++) {
        int s = __ldg(&g_ebuf[j]);
        float el = __ldg(&g_el1[s * 4 + head]);
        uint2 p = *(const uint2*)&g_feat1h[(long)s * HD + fofs];
        float w = __expf(lrelu(el + er));
        float2 f01 = __half22float2(*(__half2*)&p.x);
        float2 f23 = __half22float2(*(__half2*)&p.y);
        ax += f01.x * w; ay += f01.y * w; az += f23.x * w; aw += f23.y * w;
        wsum += w;
    }
    float inv = 1.f / fmaxf(wsum, 1e-9f);
    float4 b = *(const float4*)&b1[lane * 4];
    float4 o;
    o.x = elu1(ax * inv + b.x);
    o.y = elu1(ay * inv + b.y);
    o.z = elu1(az * inv + b.z);
    o.w = elu1(aw * inv + b.w);
    *(float4*)&g_h[(long)wid * HD + lane * 4] = o;
}

// ---------------- K3: feat2 = h @ W2 + el2/er2 --------------------------
__global__ __launch_bounds__(256) void k_gemm2(const float* __restrict__ W2,
                                               const float* __restrict__ al2,
                                               const float* __restrict__ ar2, int n) {
    __shared__ float w2s[HD * C];
    __shared__ float al2s[C], ar2s[C];
    int t = threadIdx.x;
    for (int j = t; j < HD * C; j += 256) w2s[j] = W2[j];
    if (t < C) { al2s[t] = al2[t]; ar2s[t] = ar2[t]; }
    __syncthreads();
    int node = blockIdx.x * 256 + t;
    if (node >= n) return;
    float acc[C];
#pragma unroll
    for (int c = 0; c < C; c++) acc[c] = 0.f;
    const float* hr = &g_h[(long)node * HD];
#pragma unroll 4
    for (int kk = 0; kk < 32; kk++) {
        float4 f = *(const float4*)&hr[kk * 4];
        const float* wrow = &w2s[(kk * 4) * C];
#pragma unroll
        for (int c = 0; c < C; c++) {
            acc[c] += f.x * wrow[c] + f.y * wrow[C + c] + f.z * wrow[2 * C + c] + f.w * wrow[3 * C + c];
        }
    }
    float el = 0.f, er = 0.f;
#pragma unroll
    for (int c = 0; c < C; c++) { el += acc[c] * al2s[c]; er += acc[c] * ar2s[c]; }
    __half* outp = &g_feat2h[(long)node * C];
#pragma unroll
    for (int c2 = 0; c2 < 8; c2++) {
        __half2 hv = __floats2half2_rn(acc[c2 * 2], acc[c2 * 2 + 1]);
        *(__half2*)&outp[c2 * 2] = hv;
    }
    g_el2[node] = el;
    g_er2[node] = er;
}

// ---------------- K4: fused layer-2, edge loop unrolled x4 --------------
__global__ __launch_bounds__(256) void k_layer2(const float* __restrict__ b2,
                                                float* __restrict__ out, int n) {
    int t = threadIdx.x;
    int d = blockIdx.x * 16 + (t >> 4);
    if (d >= n) return;
    int c = t & 15;
    int off0 = g_off[d], off1 = g_off[d + 1];
    float er = g_er2[d];
    float acc = 0.f, wsum = 0.f;

    int j = off0;
    for (; j + 4 <= off1; j += 4) {
        int s0 = __ldg(&g_ebuf[j]);
        int s1 = __ldg(&g_ebuf[j + 1]);
        int s2 = __ldg(&g_ebuf[j + 2]);
        int s3 = __ldg(&g_ebuf[j + 3]);
        float e0 = __ldg(&g_el2[s0]);
        float e1 = __ldg(&g_el2[s1]);
        float e2 = __ldg(&g_el2[s2]);
        float e3 = __ldg(&g_el2[s3]);
        float f0 = __half2float(g_feat2h[(long)s0 * C + c]);
        float f1 = __half2float(g_feat2h[(long)s1 * C + c]);
        float f2 = __half2float(g_feat2h[(long)s2 * C + c]);
        float f3 = __half2float(g_feat2h[(long)s3 * C + c]);
        float w0 = __expf(lrelu(e0 + er));
        float w1 = __expf(lrelu(e1 + er));
        float w2 = __expf(lrelu(e2 + er));
        float w3 = __expf(lrelu(e3 + er));
        acc += f0 * w0 + f1 * w1 + f2 * w2 + f3 * w3;
        wsum += (w0 + w1) + (w2 + w3);
    }
    for (; j < off1; j++) {
        int s = __ldg(&g_ebuf[j]);
        float el = __ldg(&g_el2[s]);
        float f = __half2float(g_feat2h[(long)s * C + c]);
        float w = __expf(lrelu(el + er));
        acc += f * w;
        wsum += w;
    }
    out[(long)d * C + c] = acc / fmaxf(wsum, 1e-9f) + __ldg(&b2[c]);
}

extern "C" void kernel_launch(void* const* d_in, const int* in_sizes, int n_in,
                              void* d_out, int out_size) {
    const float* x   = (const float*)d_in[0];
    const int*   src = (const int*)d_in[1];
    const int*   dst = (const int*)d_in[2];
    const float* W1  = (const float*)d_in[3];
    const float* b1  = (const float*)d_in[4];
    const float* al1 = (const float*)d_in[5];
    const float* ar1 = (const float*)d_in[6];
    const float* W2  = (const float*)d_in[7];
    const float* b2  = (const float*)d_in[8];
    const float* al2 = (const float*)d_in[9];
    const float* ar2 = (const float*)d_in[10];
    float* out = (float*)d_out;

    int n = in_sizes[0] / FIN;   // 50000
    int e = in_sizes[1];         // 1600000
    int eb = (e + 255) / 256;

    k_zero_cnt<<<NBLK, 256>>>();
    k_gemm1_tc<<<(n + 127) / 128, 256>>>(x, W1, al1, ar1, n);
    k_hist<<<eb, 256>>>(dst, e);
    k_scan1<<<NBLK, 256>>>();
    k_scan2<<<1, 256>>>();
    k_scan3<<<NBLK, 256>>>(e);
    k_scatter<<<eb, 256>>>(src, dst, e);

    k_layer1<<<(n * 32 + 255) / 256, 256>>>(b1, n);
    k_gemm2<<<(n + 255) / 256, 256>>>(W2, al2, ar2, n);
    k_layer2<<<(n * 16 + 255) / 256, 256>>>(b2, out, n);
}

// round 9
// speedup vs baseline: 1.3513x; 1.0344x over previous
#include <cuda_runtime.h>
#include <cuda_fp16.h>
#include <math.h>

#define NN      50000
#define EE      1600000
#define FIN     256
#define H       4
#define D       32
#define HD      128
#define C       16
#define NBLK    196     // ceil(NN/256)

// ---------------- scratch ------------------------------------------------
__device__ __align__(16) __half g_feat1h[NN * HD];
__device__ __align__(16) float g_el1[NN * H];
__device__ __align__(16) float g_er1[NN * H];
__device__ __align__(16) float g_h[NN * HD];
__device__ __align__(16) __half g_feat2h[NN * C];
__device__ __align__(16) float g_el2[NN];
__device__ __align__(16) float g_er2[NN];
// CSR build
__device__ int g_cnt[NN];
__device__ int g_off[NN + 1];
__device__ int g_cur[NN];
__device__ int g_ebuf[EE];
__device__ int g_bsum[NBLK];
__device__ int g_bpre[NBLK + 1];

__device__ __forceinline__ float lrelu(float v) { return v > 0.f ? v : 0.2f * v; }
__device__ __forceinline__ float elu1(float v)  { return v > 0.f ? v : (__expf(v) - 1.f); }

__device__ __forceinline__ void mma_f16(float c[4], unsigned a0, unsigned a1,
                                        unsigned a2, unsigned a3,
                                        unsigned b0, unsigned b1) {
    asm volatile("mma.sync.aligned.m16n8k16.row.col.f32.f16.f16.f32 "
                 "{%0,%1,%2,%3}, {%4,%5,%6,%7}, {%8,%9}, {%0,%1,%2,%3};"
                 : "+f"(c[0]), "+f"(c[1]), "+f"(c[2]), "+f"(c[3])
                 : "r"(a0), "r"(a1), "r"(a2), "r"(a3), "r"(b0), "r"(b1));
}

__device__ __forceinline__ void split2(float2 v, unsigned& hi, unsigned& lo) {
    __half2 h = __floats2half2_rn(v.x, v.y);
    float2 hb = __half22float2(h);
    __half2 l = __floats2half2_rn(v.x - hb.x, v.y - hb.y);
    hi = *(unsigned*)&h;
    lo = *(unsigned*)&l;
}

// ---------------- CSR build ---------------------------------------------
__global__ void k_zero_cnt() {
    int i = blockIdx.x * blockDim.x + threadIdx.x;
    if (i < NN) g_cnt[i] = 0;
}

__global__ void k_hist(const int* __restrict__ dst, int e_cnt) {
    int e = blockIdx.x * blockDim.x + threadIdx.x;
    if (e < e_cnt) atomicAdd(&g_cnt[dst[e]], 1);
}

__global__ void k_scan1() {
    __shared__ int sh[256];
    int t = threadIdx.x;
    int i = blockIdx.x * 256 + t;
    int v = (i < NN) ? g_cnt[i] : 0;
    sh[t] = v;
    __syncthreads();
#pragma unroll
    for (int ofs = 1; ofs < 256; ofs <<= 1) {
        int x = (t >= ofs) ? sh[t - ofs] : 0;
        __syncthreads();
        sh[t] += x;
        __syncthreads();
    }
    if (i < NN) g_off[i] = sh[t] - v;
    if (t == 255) g_bsum[blockIdx.x] = sh[255];
}

__global__ void k_scan2() {
    __shared__ int sh[256];
    int t = threadIdx.x;
    int v = (t < NBLK) ? g_bsum[t] : 0;
    sh[t] = v;
    __syncthreads();
#pragma unroll
    for (int ofs = 1; ofs < 256; ofs <<= 1) {
        int x = (t >= ofs) ? sh[t - ofs] : 0;
        __syncthreads();
        sh[t] += x;
        __syncthreads();
    }
    if (t < NBLK) g_bpre[t] = sh[t] - v;
}

__global__ void k_scan3(int e_cnt) {
    int i = blockIdx.x * blockDim.x + threadIdx.x;
    if (i < NN) {
        int o = g_off[i] + g_bpre[i >> 8];
        g_off[i] = o;
        g_cur[i] = o;
    }
    if (i == 0) g_off[NN] = e_cnt;
}

__global__ void k_scatter(const int* __restrict__ src, const int* __restrict__ dst, int e_cnt) {
    int e = blockIdx.x * blockDim.x + threadIdx.x;
    if (e >= e_cnt) return;
    int pos = atomicAdd(&g_cur[dst[e]], 1);
    g_ebuf[pos] = src[e];
}

// ---------------- K1: feat1 = x @ W1 via fp16 hi/lo HMMA ---------------
__global__ __launch_bounds__(256) void k_gemm1_tc(const float* __restrict__ x,
                                                  const float* __restrict__ W1,
                                                  const float* __restrict__ al1,
                                                  const float* __restrict__ ar1,
                                                  int n) {
    __shared__ float ws_raw[32][128];
    __shared__ uint4 wfrag[2][16][32];     // [k16][n8][lane]
    __shared__ float al_s[128], ar_s[128];
    int t = threadIdx.x;
    int lane = t & 31;
    int wid = t >> 5;
    int gid = lane >> 2;
    int tg = lane & 3;
    int warp_m = wid >> 1;
    int warp_n = wid & 1;
    int row0 = blockIdx.x * 128;
    if (t < 128) al_s[t] = al1[t];
    else         ar_s[t - 128] = ar1[t - 128];

    float acc[2][8][4];
#pragma unroll
    for (int m = 0; m < 2; m++)
#pragma unroll
        for (int j = 0; j < 8; j++) { acc[m][j][0]=0.f; acc[m][j][1]=0.f; acc[m][j][2]=0.f; acc[m][j][3]=0.f; }

    for (int kb = 0; kb < 8; kb++) {
        int K0 = kb * 32;
        unsigned Ahi[2][2][4], Alo[2][2][4];
#pragma unroll
        for (int m = 0; m < 2; m++) {
            int r = row0 + warp_m * 32 + m * 16 + gid;
            int rok0 = (r < n);
            int rok8 = (r + 8 < n);
            const float* xr0 = &x[(long)r * FIN + K0 + tg * 2];
            const float* xr8 = xr0 + 8L * FIN;
#pragma unroll
            for (int k16 = 0; k16 < 2; k16++) {
                float2 v0 = rok0 ? *(const float2*)&xr0[k16 * 16]     : make_float2(0.f, 0.f);
                float2 v1 = rok8 ? *(const float2*)&xr8[k16 * 16]     : make_float2(0.f, 0.f);
                float2 v2 = rok0 ? *(const float2*)&xr0[k16 * 16 + 8] : make_float2(0.f, 0.f);
                float2 v3 = rok8 ? *(const float2*)&xr8[k16 * 16 + 8] : make_float2(0.f, 0.f);
                split2(v0, Ahi[m][k16][0], Alo[m][k16][0]);
                split2(v1, Ahi[m][k16][1], Alo[m][k16][1]);
                split2(v2, Ahi[m][k16][2], Alo[m][k16][2]);
                split2(v3, Ahi[m][k16][3], Alo[m][k16][3]);
            }
        }
        __syncthreads();
#pragma unroll
        for (int i = 0; i < 4; i++) {
            int idx = t * 4 + i * 1024;
            int r = idx >> 7, c4 = idx & 127;
            *(float4*)&ws_raw[r][c4] = *(const float4*)&W1[(K0 + r) * HD + c4];
        }
        __syncthreads();
#pragma unroll
        for (int i = 0; i < 4; i++) {
            int e = t + i * 256;
            int k16 = e >> 9;
            int n8 = (e >> 5) & 15;
            int ln = e & 31;
            int eg = ln >> 2, et = ln & 3;
            int col = n8 * 8 + eg;
            int kr = k16 * 16 + et * 2;
            unsigned hi0, lo0, hi1, lo1;
            split2(make_float2(ws_raw[kr][col],     ws_raw[kr + 1][col]), hi0, lo0);
            split2(make_float2(ws_raw[kr + 8][col], ws_raw[kr + 9][col]), hi1, lo1);
            wfrag[k16][n8][ln] = make_uint4(hi0, hi1, lo0, lo1);
        }
        __syncthreads();
#pragma unroll
        for (int k16 = 0; k16 < 2; k16++) {
#pragma unroll
            for (int j = 0; j < 8; j++) {
                uint4 q = wfrag[k16][warp_n * 8 + j][lane];
#pragma unroll
                for (int m = 0; m < 2; m++) {
                    mma_f16(acc[m][j], Ahi[m][k16][0], Ahi[m][k16][1],
                            Ahi[m][k16][2], Ahi[m][k16][3], q.x, q.y);
                    mma_f16(acc[m][j], Ahi[m][k16][0], Ahi[m][k16][1],
                            Ahi[m][k16][2], Ahi[m][k16][3], q.z, q.w);
                    mma_f16(acc[m][j], Alo[m][k16][0], Alo[m][k16][1],
                            Alo[m][k16][2], Alo[m][k16][3], q.x, q.y);
                }
            }
        }
    }

#pragma unroll
    for (int m = 0; m < 2; m++) {
#pragma unroll
        for (int rv = 0; rv < 2; rv++) {
            int gr = row0 + warp_m * 32 + m * 16 + gid + rv * 8;
            int ci = rv * 2;
            float el0 = 0.f, er0 = 0.f, el1v = 0.f, er1v = 0.f;
#pragma unroll
            for (int j = 0; j < 8; j++) {
                int col = warp_n * 64 + j * 8 + tg * 2;
                float c0 = acc[m][j][ci], c1 = acc[m][j][ci + 1];
                float ep = c0 * al_s[col] + c1 * al_s[col + 1];
                float rp = c0 * ar_s[col] + c1 * ar_s[col + 1];
                if (j < 4) { el0 += ep; er0 += rp; }
                else       { el1v += ep; er1v += rp; }
            }
            el0 += __shfl_xor_sync(0xffffffffu, el0, 1);
            el0 += __shfl_xor_sync(0xffffffffu, el0, 2);
            er0 += __shfl_xor_sync(0xffffffffu, er0, 1);
            er0 += __shfl_xor_sync(0xffffffffu, er0, 2);
            el1v += __shfl_xor_sync(0xffffffffu, el1v, 1);
            el1v += __shfl_xor_sync(0xffffffffu, el1v, 2);
            er1v += __shfl_xor_sync(0xffffffffu, er1v, 1);
            er1v += __shfl_xor_sync(0xffffffffu, er1v, 2);
            if (gr < n) {
#pragma unroll
                for (int j = 0; j < 8; j++) {
                    int col = warp_n * 64 + j * 8 + tg * 2;
                    __half2 hv = __floats2half2_rn(acc[m][j][ci], acc[m][j][ci + 1]);
                    *(__half2*)&g_feat1h[(long)gr * HD + col] = hv;
                }
                if (tg == 0) {
                    int h0 = warp_n * 2;
                    g_el1[gr * 4 + h0] = el0;
                    g_el1[gr * 4 + h0 + 1] = el1v;
                    g_er1[gr * 4 + h0] = er0;
                    g_er1[gr * 4 + h0 + 1] = er1v;
                }
            }
        }
    }
}

// ---------------- K2: fused layer-1, edge loop unrolled x4 --------------
__global__ __launch_bounds__(256) void k_layer1(const float* __restrict__ b1, int n) {
    int wid = (blockIdx.x * blockDim.x + threadIdx.x) >> 5;
    if (wid >= n) return;
    int lane = threadIdx.x & 31;
    int head = lane >> 3;
    long fofs = lane * 4;
    int off0 = g_off[wid], off1 = g_off[wid + 1];
    float er = g_er1[wid * 4 + head];
    float ax = 0.f, ay = 0.f, az = 0.f, aw = 0.f, wsum = 0.f;

    int j = off0;
    for (; j + 4 <= off1; j += 4) {
        int s0 = __ldg(&g_ebuf[j]);
        int s1 = __ldg(&g_ebuf[j + 1]);
        int s2 = __ldg(&g_ebuf[j + 2]);
        int s3 = __ldg(&g_ebuf[j + 3]);
        float e0 = __ldg(&g_el1[s0 * 4 + head]);
        float e1 = __ldg(&g_el1[s1 * 4 + head]);
        float e2 = __ldg(&g_el1[s2 * 4 + head]);
        float e3 = __ldg(&g_el1[s3 * 4 + head]);
        uint2 p0 = *(const uint2*)&g_feat1h[(long)s0 * HD + fofs];
        uint2 p1 = *(const uint2*)&g_feat1h[(long)s1 * HD + fofs];
        uint2 p2 = *(const uint2*)&g_feat1h[(long)s2 * HD + fofs];
        uint2 p3 = *(const uint2*)&g_feat1h[(long)s3 * HD + fofs];
        float w0 = __expf(lrelu(e0 + er));
        float w1 = __expf(lrelu(e1 + er));
        float w2 = __expf(lrelu(e2 + er));
        float w3 = __expf(lrelu(e3 + er));
        wsum += (w0 + w1) + (w2 + w3);
        float2 a0 = __half22float2(*(__half2*)&p0.x), b0 = __half22float2(*(__half2*)&p0.y);
        float2 a1 = __half22float2(*(__half2*)&p1.x), b1v = __half22float2(*(__half2*)&p1.y);
        float2 a2 = __half22float2(*(__half2*)&p2.x), b2v = __half22float2(*(__half2*)&p2.y);
        float2 a3 = __half22float2(*(__half2*)&p3.x), b3v = __half22float2(*(__half2*)&p3.y);
        ax += a0.x * w0 + a1.x * w1 + a2.x * w2 + a3.x * w3;
        ay += a0.y * w0 + a1.y * w1 + a2.y * w2 + a3.y * w3;
        az += b0.x * w0 + b1v.x * w1 + b2v.x * w2 + b3v.x * w3;
        aw += b0.y * w0 + b1v.y * w1 + b2v.y * w2 + b3v.y * w3;
    }
    for (; j < off1; j++) {
        int s = __ldg(&g_ebuf[j]);
        float el = __ldg(&g_el1[s * 4 + head]);
        uint2 p = *(const uint2*)&g_feat1h[(long)s * HD + fofs];
        float w = __expf(lrelu(el + er));
        float2 f01 = __half22float2(*(__half2*)&p.x);
        float2 f23 = __half22float2(*(__half2*)&p.y);
        ax += f01.x * w; ay += f01.y * w; az += f23.x * w; aw += f23.y * w;
        wsum += w;
    }
    float inv = 1.f / fmaxf(wsum, 1e-9f);
    float4 b = *(const float4*)&b1[lane * 4];
    float4 o;
    o.x = elu1(ax * inv + b.x);
    o.y = elu1(ay * inv + b.y);
    o.z = elu1(az * inv + b.z);
    o.w = elu1(aw * inv + b.w);
    *(float4*)&g_h[(long)wid * HD + lane * 4] = o;
}

// ---------------- K3: feat2 = h @ W2 + el2/er2 --------------------------
__global__ __launch_bounds__(256) void k_gemm2(const float* __restrict__ W2,
                                               const float* __restrict__ al2,
                                               const float* __restrict__ ar2, int n) {
    __shared__ float w2s[HD * C];
    __shared__ float al2s[C], ar2s[C];
    int t = threadIdx.x;
    for (int j = t; j < HD * C; j += 256) w2s[j] = W2[j];
    if (t < C) { al2s[t] = al2[t]; ar2s[t] = ar2[t]; }
    __syncthreads();
    int node = blockIdx.x * 256 + t;
    if (node >= n) return;
    float acc[C];
#pragma unroll
    for (int c = 0; c < C; c++) acc[c] = 0.f;
    const float* hr = &g_h[(long)node * HD];
#pragma unroll 4
    for (int kk = 0; kk < 32; kk++) {
        float4 f = *(const float4*)&hr[kk * 4];
        const float* wrow = &w2s[(kk * 4) * C];
#pragma unroll
        for (int c = 0; c < C; c++) {
            acc[c] += f.x * wrow[c] + f.y * wrow[C + c] + f.z * wrow[2 * C + c] + f.w * wrow[3 * C + c];
        }
    }
    float el = 0.f, er = 0.f;
#pragma unroll
    for (int c = 0; c < C; c++) { el += acc[c] * al2s[c]; er += acc[c] * ar2s[c]; }
    __half* outp = &g_feat2h[(long)node * C];
#pragma unroll
    for (int c2 = 0; c2 < 8; c2++) {
        __half2 hv = __floats2half2_rn(acc[c2 * 2], acc[c2 * 2 + 1]);
        *(__half2*)&outp[c2 * 2] = hv;
    }
    g_el2[node] = el;
    g_er2[node] = er;
}

// ---------------- K4: fused layer-2, edge loop unrolled x4 --------------
__global__ __launch_bounds__(256) void k_layer2(const float* __restrict__ b2,
                                                float* __restrict__ out, int n) {
    int t = threadIdx.x;
    int d = blockIdx.x * 16 + (t >> 4);
    if (d >= n) return;
    int c = t & 15;
    int off0 = g_off[d], off1 = g_off[d + 1];
    float er = g_er2[d];
    float acc = 0.f, wsum = 0.f;

    int j = off0;
    for (; j + 4 <= off1; j += 4) {
        int s0 = __ldg(&g_ebuf[j]);
        int s1 = __ldg(&g_ebuf[j + 1]);
        int s2 = __ldg(&g_ebuf[j + 2]);
        int s3 = __ldg(&g_ebuf[j + 3]);
        float e0 = __ldg(&g_el2[s0]);
        float e1 = __ldg(&g_el2[s1]);
        float e2 = __ldg(&g_el2[s2]);
        float e3 = __ldg(&g_el2[s3]);
        float f0 = __half2float(g_feat2h[(long)s0 * C + c]);
        float f1 = __half2float(g_feat2h[(long)s1 * C + c]);
        float f2 = __half2float(g_feat2h[(long)s2 * C + c]);
        float f3 = __half2float(g_feat2h[(long)s3 * C + c]);
        float w0 = __expf(lrelu(e0 + er));
        float w1 = __expf(lrelu(e1 + er));
        float w2 = __expf(lrelu(e2 + er));
        float w3 = __expf(lrelu(e3 + er));
        acc += f0 * w0 + f1 * w1 + f2 * w2 + f3 * w3;
        wsum += (w0 + w1) + (w2 + w3);
    }
    for (; j < off1; j++) {
        int s = __ldg(&g_ebuf[j]);
        float el = __ldg(&g_el2[s]);
        float f = __half2float(g_feat2h[(long)s * C + c]);
        float w = __expf(lrelu(el + er));
        acc += f * w;
        wsum += w;
    }
    out[(long)d * C + c] = acc / fmaxf(wsum, 1e-9f) + __ldg(&b2[c]);
}

extern "C" void kernel_launch(void* const* d_in, const int* in_sizes, int n_in,
                              void* d_out, int out_size) {
    const float* x   = (const float*)d_in[0];
    const int*   src = (const int*)d_in[1];
    const int*   dst = (const int*)d_in[2];
    const float* W1  = (const float*)d_in[3];
    const float* b1  = (const float*)d_in[4];
    const float* al1 = (const float*)d_in[5];
    const float* ar1 = (const float*)d_in[6];
    const float* W2  = (const float*)d_in[7];
    const float* b2  = (const float*)d_in[8];
    const float* al2 = (const float*)d_in[9];
    const float* ar2 = (const float*)d_in[10];
    float* out = (float*)d_out;

    int n = in_sizes[0] / FIN;   // 50000
    int e = in_sizes[1];         // 1600000
    int eb = (e + 255) / 256;

    // one-time creation (first call is the uncaptured correctness run)
    static cudaStream_t s_csr = nullptr;
    static cudaEvent_t ev_fork = nullptr, ev_join = nullptr;
    if (s_csr == nullptr) {
        cudaStreamCreateWithFlags(&s_csr, cudaStreamNonBlocking);
        cudaEventCreateWithFlags(&ev_fork, cudaEventDisableTiming);
        cudaEventCreateWithFlags(&ev_join, cudaEventDisableTiming);
    }

    // fork: CSR build on side stream, gemm1 on main stream
    cudaEventRecord(ev_fork, 0);
    cudaStreamWaitEvent(s_csr, ev_fork, 0);

    k_zero_cnt<<<NBLK, 256, 0, s_csr>>>();
    k_hist<<<eb, 256, 0, s_csr>>>(dst, e);
    k_scan1<<<NBLK, 256, 0, s_csr>>>();
    k_scan2<<<1, 256, 0, s_csr>>>();
    k_scan3<<<NBLK, 256, 0, s_csr>>>(e);
    k_scatter<<<eb, 256, 0, s_csr>>>(src, dst, e);
    cudaEventRecord(ev_join, s_csr);

    k_gemm1_tc<<<(n + 127) / 128, 256>>>(x, W1, al1, ar1, n);

    // join: layer1 needs both gemm1 (stream 0) and CSR (s_csr)
    cudaStreamWaitEvent(0, ev_join, 0);

    k_layer1<<<(n * 32 + 255) / 256, 256>>>(b1, n);
    k_gemm2<<<(n + 255) / 256, 256>>>(W2, al2, ar2, n);
    k_layer2<<<(n * 16 + 255) / 256, 256>>>(b2, out, n);
}